// round 5
// baseline (speedup 1.0000x reference)
#include <cuda_runtime.h>
#include <cstdint>

#define HWC 4096
#define NSLICES 8192
#define GRID 888                           // 148 SM * 6 resident blocks, one wave
#define NS 10                              // ceil(8192/888)
#define NPART 32

#define CWG_F  (-2.0f    / 33554432.0f)    // -CWG_STRENGTH / (BS*HW*mh*mw)
#define DCML_F (-0.01f   / 33554432.0f)    // -DCML_STRENGTH / (BS*HW*HW)
#define TV_F   (1.0e-4f  / 16128.0f)       // TV_STRENGTH / (BS*63*64*2)
#define RCUT2  324.0f                      // 18^2; truncation ~2e-5 rel (measured-scaled)

__device__ float    g_partial[NPART];      // zero at load; last block re-zeroes
__device__ unsigned g_done;                // zero at load; last block re-zeroes

__device__ __forceinline__ float fsqrt_approx(float x) {
    float y; asm("sqrt.approx.f32 %0, %1;" : "=f"(y) : "f"(x)); return y;
}
__device__ __forceinline__ float fex2(float x) {
    float y; asm("ex2.approx.f32 %0, %1;" : "=f"(y) : "f"(x)); return y;
}

__global__ void __launch_bounds__(256) fused_kernel(
    const float* __restrict__ sim,
    const float* __restrict__ wc,
    const int*  __restrict__ mask,
    float*      __restrict__ out)
{
    const int j   = threadIdx.x;
    const int blk = blockIdx.x;
    float total = 0.0f;

    // ---- TV + DCML: blocks 0..255 each own one row/col line ----
    if (blk < 256) {
        __shared__ float c0[64], c1[64], m[64];
        const int orient = blk >> 7;       // 0: row lines (use x), 1: col lines (use y)
        const int b      = (blk >> 6) & 1;
        const int line   = blk & 63;
        if (j < 64) {
            int p = (orient == 0) ? (b * HWC + line * 64 + j)
                                  : (b * HWC + j * 64 + line);
            c0[j] = wc[2 * p + 0];
            c1[j] = wc[2 * p + 1];
            m[j]  = mask[p] ? 1.0f : 0.0f;
        }
        __syncthreads();
        if (j < 64) {
            float dc = 0.0f;
            const float vj = orient ? c0[j] : c1[j];
            if (m[j] != 0.0f) {
                for (int q = j + 1; q < 64; q++)
                    dc += fmaxf((orient ? c0[q] : c1[q]) - vj, 0.0f) * m[q];
            }
            float tv = 0.0f;
            if (j < 63) {
                const float d0 = c0[j + 1] - c0[j];
                const float d1 = c1[j + 1] - c1[j];
                tv = (d0 * d0 + d1 * d1) * m[j] * m[j + 1];
            }
            total = dc * DCML_F + tv * TV_F;
        }
        __syncthreads();
    }

    // ---- CWG: persistent stride loop over slices ----
    int msk[NS];
#pragma unroll
    for (int i = 0; i < NS; i++) {
        const int bp = blk + i * GRID;
        msk[i] = (bp < NSLICES) ? mask[bp] : 0;
    }

    const float K = -0.72134752044448169f;   // -0.5*log2(e)
    const int wbase = (j >> 5) << 7;         // warp base within each 1024-chunk
    const int lane4 = (j & 31) * 4;
    float cacc = 0.0f;

#pragma unroll 1
    for (int i = 0; i < NS; i++) {
        if (!msk[i]) continue;
        const int bp = blk + i * GRID;
        const float wcy = wc[2 * bp + 0];
        const float wcx = wc[2 * bp + 1];
        const float4* s4 = (const float4*)(sim + (size_t)bp * 4096);

        float4 v[4]; float dy2[4]; float dxa[4]; bool pr[4];
#pragma unroll
        for (int p = 0; p < 4; p++) {         // front-batched predicated loads (MLP=4)
            const int idx = p * 1024 + wbase + lane4;
            const float dy = (float)(idx >> 6) - wcy;
            dy2[p] = dy * dy;
            const float a = (float)(idx & 63) - wcx;   // dx of first of 4 cols
            dxa[p] = a;
            const float dxn = fmaxf(fmaxf(a, -a - 3.0f), 0.0f);  // nearest |dx|
            pr[p] = (dy2[p] + dxn * dxn) < RCUT2;
            v[p] = pr[p] ? s4[idx >> 2] : make_float4(0.f, 0.f, 0.f, 0.f);
        }
#pragma unroll
        for (int p = 0; p < 4; p++) {
            if (pr[p]) {
                const float d2 = dy2[p];
                const float a  = dxa[p];
                cacc += v[p].x * fex2(K * fsqrt_approx(d2 + a * a));
                cacc += v[p].y * fex2(K * fsqrt_approx(d2 + (a + 1.f) * (a + 1.f)));
                cacc += v[p].z * fex2(K * fsqrt_approx(d2 + (a + 2.f) * (a + 2.f)));
                cacc += v[p].w * fex2(K * fsqrt_approx(d2 + (a + 3.f) * (a + 3.f)));
            }
        }
    }
    total += cacc * CWG_F;

    // ---- block reduce + global accumulate + last-block finalize ----
#pragma unroll
    for (int o = 16; o; o >>= 1) total += __shfl_down_sync(0xffffffffu, total, o);
    __shared__ float sh[8];
    __shared__ bool  s_last;
    if ((j & 31) == 0) sh[j >> 5] = total;
    __syncthreads();
    if (j == 0) {
        float s = 0.0f;
#pragma unroll
        for (int w = 0; w < 8; w++) s += sh[w];
        atomicAdd(&g_partial[blk & (NPART - 1)], s);
        __threadfence();
        const unsigned t = atomicAdd(&g_done, 1u);
        s_last = (t == (unsigned)(GRID - 1));
    }
    __syncthreads();
    if (s_last && j < NPART) {
        float v = atomicExch(&g_partial[j], 0.0f);   // read + reset for next replay
#pragma unroll
        for (int o = 16; o; o >>= 1) v += __shfl_down_sync(0xffffffffu, v, o);
        if (j == 0) {
            out[0] = v;
            atomicExch(&g_done, 0u);                 // reset ticket for next replay
        }
    }
}

extern "C" void kernel_launch(void* const* d_in, const int* in_sizes, int n_in,
                              void* d_out, int out_size)
{
    const float* sim  = (const float*)d_in[0];
    const float* wc   = (const float*)d_in[1];
    const int*   mask = (const int*)d_in[2];
    float* out = (float*)d_out;

    fused_kernel<<<GRID, 256>>>(sim, wc, mask, out);
}

// round 6
// speedup vs baseline: 1.0034x; 1.0034x over previous
#include <cuda_runtime.h>
#include <cstdint>

#define HWC 4096
#define NSLICES 8192
#define GRID 888
#define NS 10                              // ceil(8192/888)
#define NPART 32

#define CWG_F  (-2.0f    / 33554432.0f)
#define DCML_F (-0.01f   / 33554432.0f)
#define TV_F   (1.0e-4f  / 16128.0f)
#define RCUT2  324.0f                      // 18^2

__device__ float    g_partial[NPART];
__device__ unsigned g_done;

__device__ __forceinline__ float fsqrt_approx(float x) {
    float y; asm("sqrt.approx.f32 %0, %1;" : "=f"(y) : "f"(x)); return y;
}
__device__ __forceinline__ float fex2(float x) {
    float y; asm("ex2.approx.f32 %0, %1;" : "=f"(y) : "f"(x)); return y;
}

__global__ void __launch_bounds__(256) fused_kernel(
    const float* __restrict__ sim,
    const float* __restrict__ wc,
    const int*  __restrict__ mask,
    float*      __restrict__ out)
{
    const int j   = threadIdx.x;
    const int blk = blockIdx.x;
    float total = 0.0f;

    // ---- TV + DCML: blocks 0..255 each own one row/col line ----
    if (blk < 256) {
        __shared__ float c0[64], c1[64], m[64];
        const int orient = blk >> 7;
        const int b      = (blk >> 6) & 1;
        const int line   = blk & 63;
        if (j < 64) {
            int p = (orient == 0) ? (b * HWC + line * 64 + j)
                                  : (b * HWC + j * 64 + line);
            c0[j] = wc[2 * p + 0];
            c1[j] = wc[2 * p + 1];
            m[j]  = mask[p] ? 1.0f : 0.0f;
        }
        __syncthreads();
        if (j < 64) {
            float dc = 0.0f;
            const float vj = orient ? c0[j] : c1[j];
            if (m[j] != 0.0f) {
                for (int q = j + 1; q < 64; q++)
                    dc += fmaxf((orient ? c0[q] : c1[q]) - vj, 0.0f) * m[q];
            }
            float tv = 0.0f;
            if (j < 63) {
                const float d0 = c0[j + 1] - c0[j];
                const float d1 = c1[j + 1] - c1[j];
                tv = (d0 * d0 + d1 * d1) * m[j] * m[j + 1];
            }
            total = dc * DCML_F + tv * TV_F;
        }
        __syncthreads();
    }

    // ---- CWG: persistent, 2-deep software-pipelined over active slices ----
    // slice-invariant per-thread geometry
    const int toff  = ((j >> 5) << 7) + ((j & 31) << 2);  // element offset in 1024-chunk
    const float colf = (float)(toff & 63);
    float rowf[4];
#pragma unroll
    for (int p = 0; p < 4; p++) rowf[p] = (float)((p * 1024 + toff) >> 6);

    // active-slice bitmask (block-uniform)
    unsigned mb = 0;
#pragma unroll
    for (int i = 0; i < NS; i++) {
        const int bp = blk + i * GRID;
        if (bp < NSLICES && mask[bp]) mb |= 1u << i;
    }

    const float K = -0.72134752044448169f;   // -0.5*log2(e)
    const float4 f40 = make_float4(0.f, 0.f, 0.f, 0.f);
    float cacc = 0.0f;

    float4 vA[4], vB[4];
    float  dyA[4], dyB[4];
    bool   prA[4], prB[4];
    float  wxA = 0.f, wxB = 0.f;

#define ISSUE(ii, V, PR, DY2, WX) do {                                      \
        const int bp_ = blk + (ii) * GRID;                                  \
        const float wcy_ = __ldg(&wc[2 * bp_]);                             \
        WX = __ldg(&wc[2 * bp_ + 1]);                                       \
        const float4* s4_ = (const float4*)(sim + (size_t)bp_ * 4096);      \
        _Pragma("unroll")                                                   \
        for (int p = 0; p < 4; p++) {                                       \
            const float dy_ = rowf[p] - wcy_;                               \
            DY2[p] = dy_ * dy_;                                             \
            const float a_ = colf - WX;                                     \
            const float dxn_ = fmaxf(fmaxf(a_, -a_ - 3.0f), 0.0f);          \
            PR[p] = (DY2[p] + dxn_ * dxn_) < RCUT2;                         \
            V[p] = PR[p] ? s4_[(p * 1024 + toff) >> 2] : f40;               \
        }                                                                   \
    } while (0)

#define COMPUTE(V, PR, DY2, WX) do {                                        \
        const float a0_ = colf - WX;                                        \
        _Pragma("unroll")                                                   \
        for (int p = 0; p < 4; p++) {                                       \
            if (PR[p]) {                                                    \
                const float d2_ = DY2[p];                                   \
                cacc += V[p].x * fex2(K * fsqrt_approx(d2_ + a0_ * a0_));                   \
                cacc += V[p].y * fex2(K * fsqrt_approx(d2_ + (a0_+1.f) * (a0_+1.f)));       \
                cacc += V[p].z * fex2(K * fsqrt_approx(d2_ + (a0_+2.f) * (a0_+2.f)));       \
                cacc += V[p].w * fex2(K * fsqrt_approx(d2_ + (a0_+3.f) * (a0_+3.f)));       \
            }                                                               \
        }                                                                   \
    } while (0)

    int ia = -1, ib = -1;
    if (mb) { ia = __ffs(mb) - 1; mb &= mb - 1; ISSUE(ia, vA, prA, dyA, wxA); }
    while (ia >= 0) {
        ib = -1;
        if (mb) { ib = __ffs(mb) - 1; mb &= mb - 1; ISSUE(ib, vB, prB, dyB, wxB); }
        COMPUTE(vA, prA, dyA, wxA);
        ia = -1;
        if (ib >= 0) {
            if (mb) { ia = __ffs(mb) - 1; mb &= mb - 1; ISSUE(ia, vA, prA, dyA, wxA); }
            COMPUTE(vB, prB, dyB, wxB);
        }
    }
#undef ISSUE
#undef COMPUTE

    total += cacc * CWG_F;

    // ---- block reduce + global accumulate + last-block finalize ----
#pragma unroll
    for (int o = 16; o; o >>= 1) total += __shfl_down_sync(0xffffffffu, total, o);
    __shared__ float sh[8];
    __shared__ bool  s_last;
    if ((j & 31) == 0) sh[j >> 5] = total;
    __syncthreads();
    if (j == 0) {
        float s = 0.0f;
#pragma unroll
        for (int w = 0; w < 8; w++) s += sh[w];
        atomicAdd(&g_partial[blk & (NPART - 1)], s);
        __threadfence();
        const unsigned t = atomicAdd(&g_done, 1u);
        s_last = (t == (unsigned)(GRID - 1));
    }
    __syncthreads();
    if (s_last && j < NPART) {
        float v = atomicExch(&g_partial[j], 0.0f);
#pragma unroll
        for (int o = 16; o; o >>= 1) v += __shfl_down_sync(0xffffffffu, v, o);
        if (j == 0) {
            out[0] = v;
            atomicExch(&g_done, 0u);
        }
    }
}

extern "C" void kernel_launch(void* const* d_in, const int* in_sizes, int n_in,
                              void* d_out, int out_size)
{
    const float* sim  = (const float*)d_in[0];
    const float* wc   = (const float*)d_in[1];
    const int*   mask = (const int*)d_in[2];
    float* out = (float*)d_out;

    fused_kernel<<<GRID, 256>>>(sim, wc, mask, out);
}